// round 11
// baseline (speedup 1.0000x reference)
#include <cuda_runtime.h>
#include <cstdint>

// Problem constants
#define E_   32
#define H_   512
#define I_   1024
#define T_   4096
#define TK   8192        // T*K
#define CAP_ 512
#define EC   (E_ * CAP_) // 16384 padded rows

// ---------------- device scratch (BSS, zero-init at module load) ----------------
__device__ float g_xd[(size_t)EC * H_];          // gathered tokens   [EC, 512]   32 MB
__device__ float g_gu[(size_t)EC * 2 * I_];      // gate_up result    [EC, 2048] 128 MB
__device__ float g_act[(size_t)EC * I_];         // swiglu result     [EC, 1024]  64 MB
__device__ float g_y[(size_t)EC * H_];           // expert output     [EC, 512]   32 MB
__device__ int   g_cnt[E_];
__device__ int   g_row[TK];                      // slot -> padded row (-1 = invalid)
__device__ int   g_mode64;                       // 1 if indices are int64, 0 if int32

// ---------------- dtype detect + zero counters ----------------
// Reads only the first 8192 int32 words of the index buffer (safe for both
// int32 [8192 words] and int64 [16384 words] layouts). For little-endian int64
// with values < 32, every odd word is a zero hi-word; for int32 random indices
// in [0,32), the OR of 4096 odd-position values is nonzero w.p. 1.
__global__ void k_detect(const int* __restrict__ idx32) {
    __shared__ int s_or;
    if (threadIdx.x == 0) s_or = 0;
    if (threadIdx.x < E_) g_cnt[threadIdx.x] = 0;
    __syncthreads();
    int acc = 0;
    for (int i = threadIdx.x; i < TK / 2; i += blockDim.x)
        acc |= idx32[2 * i + 1];
    atomicOr(&s_or, acc);
    __syncthreads();
    if (threadIdx.x == 0) g_mode64 = (s_or == 0) ? 1 : 0;
}

__global__ void k_dispatch(const void* __restrict__ idx_raw) {
    int s = blockIdx.x * blockDim.x + threadIdx.x;
    if (s >= TK) return;
    long long e;
    if (g_mode64) e = ((const long long*)idx_raw)[s];
    else          e = (long long)((const int*)idx_raw)[s];
    if (e < 0 || e >= E_) { g_row[s] = -1; return; }   // range guard: never form wild atomics
    int pos = atomicAdd(&g_cnt[(int)e], 1);
    g_row[s] = (pos < CAP_) ? ((int)e * CAP_ + pos) : -1;
}

// one block per slot, 128 threads, H/4 = 128 float4 per row
__global__ void k_gather(const float* __restrict__ hidden) {
    int s = blockIdx.x;
    int r = g_row[s];
    if (r < 0) return;
    int t = s >> 1;  // K = 2
    const float4* src = (const float4*)(hidden + (size_t)t * H_);
    float4* dst = (float4*)(g_xd + (size_t)r * H_);
    dst[threadIdx.x] = src[threadIdx.x];
}

// ---------------- grouped GEMM: C[e] = A[e] * W[e]^T, all operands K-contiguous ----------------
// BM=BN=128, BK=16, 256 threads, 8x8 microtile as f32x2 pairs along N.
#define BM 128
#define BN 128
#define BK 16

// WHICH==0: A=g_xd (K=512),  C=g_gu, NDIM=2048   (gate_up)
// WHICH==1: A=g_act (K=1024), C=g_y, NDIM=512    (down)
template <int KDIM, int WHICH>
__global__ __launch_bounds__(256, 2) void k_gemm(const float* __restrict__ W) {
    constexpr int NDIM = (WHICH == 0) ? (2 * I_) : H_;
    const float* __restrict__ A = (WHICH == 0) ? g_xd : g_act;
    float* __restrict__ C       = (WHICH == 0) ? g_gu : g_y;

    int e = blockIdx.z;
    int n_e = g_cnt[e];
    if (n_e > CAP_) n_e = CAP_;
    int m0 = blockIdx.y * BM;
    if (m0 >= n_e) return;       // skip tiles with no routed rows
    int n0 = blockIdx.x * BN;

    const float* Ae = A + ((size_t)e * CAP_ + m0) * KDIM;
    const float* We = W + ((size_t)e * NDIM + n0) * KDIM;
    float* Ce       = C + ((size_t)e * CAP_ + m0) * NDIM + n0;

    __shared__ __align__(16) float As[2][BK][BM];
    __shared__ __align__(16) float Bs[2][BK][BN];

    int tid  = threadIdx.x;
    int lrow = tid & 127;        // load: row within tile
    int lkv  = tid >> 7;         // load: which 4-float k-chunk (0/1, +2 on 2nd pass)
    int tx   = tid & 15;         // compute: n-group
    int ty   = tid >> 4;         // compute: m-group

    unsigned long long acc[8][4];
#pragma unroll
    for (int i = 0; i < 8; i++)
#pragma unroll
        for (int j = 0; j < 4; j++) acc[i][j] = 0ull;

    float4 ra[2], rb[2];

    auto prefetch = [&](int kt) {
#pragma unroll
        for (int i = 0; i < 2; i++) {
            int kk = (lkv + 2 * i) * 4;
            ra[i] = *(const float4*)(Ae + (size_t)lrow * KDIM + kt + kk);
            rb[i] = *(const float4*)(We + (size_t)lrow * KDIM + kt + kk);
        }
    };
    auto stage = [&](int buf) {
#pragma unroll
        for (int i = 0; i < 2; i++) {
            int kk = (lkv + 2 * i) * 4;
            As[buf][kk + 0][lrow] = ra[i].x;
            As[buf][kk + 1][lrow] = ra[i].y;
            As[buf][kk + 2][lrow] = ra[i].z;
            As[buf][kk + 3][lrow] = ra[i].w;
            Bs[buf][kk + 0][lrow] = rb[i].x;
            Bs[buf][kk + 1][lrow] = rb[i].y;
            Bs[buf][kk + 2][lrow] = rb[i].z;
            Bs[buf][kk + 3][lrow] = rb[i].w;
        }
    };

    prefetch(0);
    stage(0);
    __syncthreads();

    constexpr int NK = KDIM / BK;
    for (int t = 0; t < NK; t++) {
        int buf = t & 1;
        if (t + 1 < NK) prefetch((t + 1) * BK);
#pragma unroll
        for (int k = 0; k < BK; k++) {
            const float* ap = &As[buf][k][ty * 8];
            float4 a0 = *(const float4*)ap;
            float4 a1 = *(const float4*)(ap + 4);
            const float* bpp = &Bs[buf][k][tx * 8];
            ulonglong2 b0 = *(const ulonglong2*)bpp;        // LDS.128 -> 2 packed f32x2
            ulonglong2 b1 = *(const ulonglong2*)(bpp + 4);
            unsigned long long bp[4] = {b0.x, b0.y, b1.x, b1.y};
            float av[8] = {a0.x, a0.y, a0.z, a0.w, a1.x, a1.y, a1.z, a1.w};
#pragma unroll
            for (int i = 0; i < 8; i++) {
                unsigned long long ad;
                unsigned int au = __float_as_uint(av[i]);
                asm("mov.b64 %0, {%1, %1};" : "=l"(ad) : "r"(au));  // broadcast a into both halves
#pragma unroll
                for (int j = 0; j < 4; j++)
                    asm("fma.rn.f32x2 %0, %1, %2, %0;"
                        : "+l"(acc[i][j]) : "l"(ad), "l"(bp[j]));
            }
        }
        if (t + 1 < NK) stage((t + 1) & 1);
        __syncthreads();
    }

    // epilogue: acc[i][j] holds C[m][n+2j], C[m][n+2j+1]
#pragma unroll
    for (int i = 0; i < 8; i++) {
        float* cr = Ce + (size_t)(ty * 8 + i) * NDIM + tx * 8;
        ulonglong2 v0; v0.x = acc[i][0]; v0.y = acc[i][1];
        ulonglong2 v1; v1.x = acc[i][2]; v1.y = acc[i][3];
        *(ulonglong2*)cr = v0;
        *(ulonglong2*)(cr + 4) = v1;
    }
}

// ---------------- SwiGLU: act = silu(gate) * up ----------------
__global__ void k_swiglu() {
    int idx = blockIdx.x * blockDim.x + threadIdx.x;  // over EC * (I/4) = 16384*256
    int r = idx >> 8;          // I/4 = 256 float4 per row
    int c = idx & 255;
    const float4* gu4 = (const float4*)g_gu;
    float4 g = gu4[(size_t)r * 512 + c];        // gate: cols [0, I)
    float4 u = gu4[(size_t)r * 512 + 256 + c];  // up:   cols [I, 2I)
    float4 o;
    o.x = (g.x / (1.f + __expf(-g.x))) * u.x;
    o.y = (g.y / (1.f + __expf(-g.y))) * u.y;
    o.z = (g.z / (1.f + __expf(-g.z))) * u.z;
    o.w = (g.w / (1.f + __expf(-g.w))) * u.w;
    ((float4*)g_act)[(size_t)r * 256 + c] = o;
}

// ---------------- combine: out[t] = sum_k w[t,k] * y[row(t,k)] ----------------
__global__ void k_combine(const float* __restrict__ wts, float* __restrict__ out) {
    int t = blockIdx.x;
    int r0 = g_row[2 * t];
    int r1 = g_row[2 * t + 1];
    float w0 = wts[2 * t];
    float w1 = wts[2 * t + 1];
    int j = threadIdx.x;  // 0..127 (H/4)
    float4 v = {0.f, 0.f, 0.f, 0.f};
    if (r0 >= 0) {
        float4 y = ((const float4*)g_y)[(size_t)r0 * 128 + j];
        v.x += w0 * y.x; v.y += w0 * y.y; v.z += w0 * y.z; v.w += w0 * y.w;
    }
    if (r1 >= 0) {
        float4 y = ((const float4*)g_y)[(size_t)r1 * 128 + j];
        v.x += w1 * y.x; v.y += w1 * y.y; v.z += w1 * y.z; v.w += w1 * y.w;
    }
    ((float4*)out)[(size_t)t * 128 + j] = v;
}

// ---------------- launch ----------------
extern "C" void kernel_launch(void* const* d_in, const int* in_sizes, int n_in,
                              void* d_out, int out_size) {
    const float* hidden = (const float*)d_in[0];      // [4096, 512]
    const void*  idx    = d_in[1];                    // [4096, 2] int64 OR int32 (auto-detected)
    const float* wts    = (const float*)d_in[2];      // [4096, 2]
    const float* gup    = (const float*)d_in[3];      // [32, 2048, 512]
    const float* down   = (const float*)d_in[4];      // [32, 512, 1024]
    float*       out    = (float*)d_out;              // [4096, 512]

    k_detect<<<1, 256>>>((const int*)idx);
    k_dispatch<<<TK / 256, 256>>>(idx);
    k_gather<<<TK, 128>>>(hidden);

    // GEMM1: [EC,512] x [E,2048,512]^T -> [EC,2048]
    k_gemm<512, 0><<<dim3(2 * I_ / BN, CAP_ / BM, E_), 256>>>(gup);

    // SwiGLU over EC * I/4 elements
    k_swiglu<<<(EC * (I_ / 4)) / 256, 256>>>();

    // GEMM2: [EC,1024] x [E,512,1024]^T -> [EC,512]
    k_gemm<1024, 1><<<dim3(H_ / BN, CAP_ / BM, E_), 256>>>(down);

    k_combine<<<T_, 128>>>(wts, out);
}

// round 12
// speedup vs baseline: 1.3460x; 1.3460x over previous
#include <cuda_runtime.h>
#include <cstdint>

// Problem constants
#define E_   32
#define H_   512
#define I_   1024
#define T_   4096
#define TK   8192        // T*K
#define CAP_ 512
#define EC   (E_ * CAP_) // 16384 padded rows

// ---------------- device scratch (BSS, zero-init at module load) ----------------
__device__ float g_xd[(size_t)EC * H_];          // gathered tokens   [EC, 512]   32 MB
__device__ float g_act[(size_t)EC * I_];         // swiglu result     [EC, 1024]  64 MB
__device__ float g_y[(size_t)EC * H_];           // expert output     [EC, 512]   32 MB
__device__ int   g_cnt[E_];
__device__ int   g_row[TK];                      // slot -> padded row (-1 = invalid)
__device__ int   g_mode64;                       // 1 if indices are int64, 0 if int32

__device__ __forceinline__ float2 unpack64(unsigned long long v) {
    float2 r;
    asm("mov.b64 {%0, %1}, %2;" : "=f"(r.x), "=f"(r.y) : "l"(v));
    return r;
}

// ---------------- dtype detect + zero counters ----------------
__global__ void k_detect(const int* __restrict__ idx32) {
    __shared__ int s_or;
    if (threadIdx.x == 0) s_or = 0;
    if (threadIdx.x < E_) g_cnt[threadIdx.x] = 0;
    __syncthreads();
    int acc = 0;
    for (int i = threadIdx.x; i < TK / 2; i += blockDim.x)
        acc |= idx32[2 * i + 1];
    atomicOr(&s_or, acc);
    __syncthreads();
    if (threadIdx.x == 0) g_mode64 = (s_or == 0) ? 1 : 0;
}

__global__ void k_dispatch(const void* __restrict__ idx_raw) {
    int s = blockIdx.x * blockDim.x + threadIdx.x;
    if (s >= TK) return;
    long long e;
    if (g_mode64) e = ((const long long*)idx_raw)[s];
    else          e = (long long)((const int*)idx_raw)[s];
    if (e < 0 || e >= E_) { g_row[s] = -1; return; }
    int pos = atomicAdd(&g_cnt[(int)e], 1);
    g_row[s] = (pos < CAP_) ? ((int)e * CAP_ + pos) : -1;
}

// one block per slot, 128 threads, H/4 = 128 float4 per row
__global__ void k_gather(const float* __restrict__ hidden) {
    int s = blockIdx.x;
    int r = g_row[s];
    if (r < 0) return;
    int t = s >> 1;  // K = 2
    const float4* src = (const float4*)(hidden + (size_t)t * H_);
    float4* dst = (float4*)(g_xd + (size_t)r * H_);
    dst[threadIdx.x] = src[threadIdx.x];
}

// =====================================================================
// GEMM1 fused with SwiGLU.
// Block: BM=64 rows x (64 gate + 64 up) columns, K=512, BK=16, 128 thr.
// Per thread: 8(m) x 4(gate) + 8 x 4(up) accumulators as f32x2 pairs.
// act[m][n] = silu(gate[m][n]) * up[m][n], written directly to g_act.
// =====================================================================
__global__ __launch_bounds__(128, 4) void k_gemm1(const float* __restrict__ W) {
    int e = blockIdx.z;
    int n_e = g_cnt[e]; if (n_e > CAP_) n_e = CAP_;
    int m0 = blockIdx.y * 64;
    if (m0 >= n_e) return;
    int n0 = blockIdx.x * 64;

    const float* Ae = g_xd + ((size_t)e * CAP_ + m0) * 512;
    const float* Wg = W + ((size_t)e * 2048 + n0) * 512;          // gate rows
    const float* Wu = W + ((size_t)e * 2048 + 1024 + n0) * 512;   // up rows
    float* Ce = g_act + ((size_t)e * CAP_ + m0) * 1024 + n0;

    __shared__ __align__(16) float As[2][16][64];
    __shared__ __align__(16) float Bs[2][16][128];

    int tid = threadIdx.x;
    int l = tid & 31, w = tid >> 5;      // loader: lane-row, k-chunk
    int tx = tid & 15, ty = tid >> 4;    // compute: n-group, m-group

    // loader base pointers (k-chunk = w, i.e. floats [w*4, w*4+4) of each BK tile)
    const float* ap0 = Ae + (size_t)l * 512 + w * 4;
    const float* ap1 = ap0 + (size_t)32 * 512;
    const float* bp[4];
#pragma unroll
    for (int i = 0; i < 4; i++) {
        int br = l + 32 * i;
        bp[i] = ((br < 64) ? (Wg + (size_t)br * 512)
                           : (Wu + (size_t)(br - 64) * 512)) + w * 4;
    }

    unsigned long long accg[8][2], accu[8][2];
#pragma unroll
    for (int i = 0; i < 8; i++) {
        accg[i][0] = accg[i][1] = 0ull;
        accu[i][0] = accu[i][1] = 0ull;
    }

    float4 ra0, ra1, rb[4];
    auto prefetch = [&](int kt) {
        ra0 = *(const float4*)(ap0 + kt);
        ra1 = *(const float4*)(ap1 + kt);
#pragma unroll
        for (int i = 0; i < 4; i++) rb[i] = *(const float4*)(bp[i] + kt);
    };
    auto stage = [&](int buf) {
        As[buf][w * 4 + 0][l] = ra0.x;  As[buf][w * 4 + 1][l] = ra0.y;
        As[buf][w * 4 + 2][l] = ra0.z;  As[buf][w * 4 + 3][l] = ra0.w;
        As[buf][w * 4 + 0][l + 32] = ra1.x;  As[buf][w * 4 + 1][l + 32] = ra1.y;
        As[buf][w * 4 + 2][l + 32] = ra1.z;  As[buf][w * 4 + 3][l + 32] = ra1.w;
#pragma unroll
        for (int i = 0; i < 4; i++) {
            Bs[buf][w * 4 + 0][l + 32 * i] = rb[i].x;
            Bs[buf][w * 4 + 1][l + 32 * i] = rb[i].y;
            Bs[buf][w * 4 + 2][l + 32 * i] = rb[i].z;
            Bs[buf][w * 4 + 3][l + 32 * i] = rb[i].w;
        }
    };

    prefetch(0);
    stage(0);
    __syncthreads();

    const int NK = 512 / 16;
    for (int t = 0; t < NK; t++) {
        int buf = t & 1;
        if (t + 1 < NK) prefetch((t + 1) * 16);
#pragma unroll
        for (int k = 0; k < 16; k++) {
            float4 a0 = *(const float4*)&As[buf][k][ty * 8];
            float4 a1 = *(const float4*)&As[buf][k][ty * 8 + 4];
            ulonglong2 bg = *(const ulonglong2*)&Bs[buf][k][tx * 4];
            ulonglong2 bu = *(const ulonglong2*)&Bs[buf][k][64 + tx * 4];
            float av[8] = {a0.x, a0.y, a0.z, a0.w, a1.x, a1.y, a1.z, a1.w};
#pragma unroll
            for (int i = 0; i < 8; i++) {
                unsigned long long ad;
                unsigned int au = __float_as_uint(av[i]);
                asm("mov.b64 %0, {%1, %1};" : "=l"(ad) : "r"(au));
                asm("fma.rn.f32x2 %0, %1, %2, %0;" : "+l"(accg[i][0]) : "l"(ad), "l"(bg.x));
                asm("fma.rn.f32x2 %0, %1, %2, %0;" : "+l"(accg[i][1]) : "l"(ad), "l"(bg.y));
                asm("fma.rn.f32x2 %0, %1, %2, %0;" : "+l"(accu[i][0]) : "l"(ad), "l"(bu.x));
                asm("fma.rn.f32x2 %0, %1, %2, %0;" : "+l"(accu[i][1]) : "l"(ad), "l"(bu.y));
            }
        }
        if (t + 1 < NK) stage((t + 1) & 1);
        __syncthreads();
    }

    // fused SwiGLU epilogue: act = silu(gate) * up
#pragma unroll
    for (int i = 0; i < 8; i++) {
        float2 g01 = unpack64(accg[i][0]);
        float2 g23 = unpack64(accg[i][1]);
        float2 u01 = unpack64(accu[i][0]);
        float2 u23 = unpack64(accu[i][1]);
        float4 o;
        o.x = (g01.x / (1.f + __expf(-g01.x))) * u01.x;
        o.y = (g01.y / (1.f + __expf(-g01.y))) * u01.y;
        o.z = (g23.x / (1.f + __expf(-g23.x))) * u23.x;
        o.w = (g23.y / (1.f + __expf(-g23.y))) * u23.y;
        *(float4*)(Ce + (size_t)(ty * 8 + i) * 1024 + tx * 4) = o;
    }
}

// =====================================================================
// GEMM2: y[e] = act[e] (EC x 1024) * down[e]^T (512 x 1024).
// Block: BM=64 x BN=128, K=1024, BK=16, 128 thr, 8x8 microtile.
// =====================================================================
__global__ __launch_bounds__(128, 4) void k_gemm2(const float* __restrict__ W) {
    int e = blockIdx.z;
    int n_e = g_cnt[e]; if (n_e > CAP_) n_e = CAP_;
    int m0 = blockIdx.y * 64;
    if (m0 >= n_e) return;
    int n0 = blockIdx.x * 128;

    const float* Ae = g_act + ((size_t)e * CAP_ + m0) * 1024;
    const float* We = W + ((size_t)e * 512 + n0) * 1024;
    float* Ce = g_y + ((size_t)e * CAP_ + m0) * 512 + n0;

    __shared__ __align__(16) float As[2][16][64];
    __shared__ __align__(16) float Bs[2][16][128];

    int tid = threadIdx.x;
    int l = tid & 31, w = tid >> 5;
    int tx = tid & 15, ty = tid >> 4;

    const float* ap0 = Ae + (size_t)l * 1024 + w * 4;
    const float* ap1 = ap0 + (size_t)32 * 1024;
    const float* bp[4];
#pragma unroll
    for (int i = 0; i < 4; i++)
        bp[i] = We + (size_t)(l + 32 * i) * 1024 + w * 4;

    unsigned long long acc[8][4];
#pragma unroll
    for (int i = 0; i < 8; i++)
#pragma unroll
        for (int j = 0; j < 4; j++) acc[i][j] = 0ull;

    float4 ra0, ra1, rb[4];
    auto prefetch = [&](int kt) {
        ra0 = *(const float4*)(ap0 + kt);
        ra1 = *(const float4*)(ap1 + kt);
#pragma unroll
        for (int i = 0; i < 4; i++) rb[i] = *(const float4*)(bp[i] + kt);
    };
    auto stage = [&](int buf) {
        As[buf][w * 4 + 0][l] = ra0.x;  As[buf][w * 4 + 1][l] = ra0.y;
        As[buf][w * 4 + 2][l] = ra0.z;  As[buf][w * 4 + 3][l] = ra0.w;
        As[buf][w * 4 + 0][l + 32] = ra1.x;  As[buf][w * 4 + 1][l + 32] = ra1.y;
        As[buf][w * 4 + 2][l + 32] = ra1.z;  As[buf][w * 4 + 3][l + 32] = ra1.w;
#pragma unroll
        for (int i = 0; i < 4; i++) {
            Bs[buf][w * 4 + 0][l + 32 * i] = rb[i].x;
            Bs[buf][w * 4 + 1][l + 32 * i] = rb[i].y;
            Bs[buf][w * 4 + 2][l + 32 * i] = rb[i].z;
            Bs[buf][w * 4 + 3][l + 32 * i] = rb[i].w;
        }
    };

    prefetch(0);
    stage(0);
    __syncthreads();

    const int NK = 1024 / 16;
    for (int t = 0; t < NK; t++) {
        int buf = t & 1;
        if (t + 1 < NK) prefetch((t + 1) * 16);
#pragma unroll
        for (int k = 0; k < 16; k++) {
            float4 a0 = *(const float4*)&As[buf][k][ty * 8];
            float4 a1 = *(const float4*)&As[buf][k][ty * 8 + 4];
            ulonglong2 b0 = *(const ulonglong2*)&Bs[buf][k][tx * 8];
            ulonglong2 b1 = *(const ulonglong2*)&Bs[buf][k][tx * 8 + 4];
            unsigned long long bpk[4] = {b0.x, b0.y, b1.x, b1.y};
            float av[8] = {a0.x, a0.y, a0.z, a0.w, a1.x, a1.y, a1.z, a1.w};
#pragma unroll
            for (int i = 0; i < 8; i++) {
                unsigned long long ad;
                unsigned int au = __float_as_uint(av[i]);
                asm("mov.b64 %0, {%1, %1};" : "=l"(ad) : "r"(au));
#pragma unroll
                for (int j = 0; j < 4; j++)
                    asm("fma.rn.f32x2 %0, %1, %2, %0;"
                        : "+l"(acc[i][j]) : "l"(ad), "l"(bpk[j]));
            }
        }
        if (t + 1 < NK) stage((t + 1) & 1);
        __syncthreads();
    }

#pragma unroll
    for (int i = 0; i < 8; i++) {
        float* cr = Ce + (size_t)(ty * 8 + i) * 512 + tx * 8;
        ulonglong2 v0; v0.x = acc[i][0]; v0.y = acc[i][1];
        ulonglong2 v1; v1.x = acc[i][2]; v1.y = acc[i][3];
        *(ulonglong2*)cr = v0;
        *(ulonglong2*)(cr + 4) = v1;
    }
}

// ---------------- combine: out[t] = sum_k w[t,k] * y[row(t,k)] ----------------
__global__ void k_combine(const float* __restrict__ wts, float* __restrict__ out) {
    int t = blockIdx.x;
    int r0 = g_row[2 * t];
    int r1 = g_row[2 * t + 1];
    float w0 = wts[2 * t];
    float w1 = wts[2 * t + 1];
    int j = threadIdx.x;  // 0..127 (H/4)
    float4 v = {0.f, 0.f, 0.f, 0.f};
    if (r0 >= 0) {
        float4 y = ((const float4*)g_y)[(size_t)r0 * 128 + j];
        v.x += w0 * y.x; v.y += w0 * y.y; v.z += w0 * y.z; v.w += w0 * y.w;
    }
    if (r1 >= 0) {
        float4 y = ((const float4*)g_y)[(size_t)r1 * 128 + j];
        v.x += w1 * y.x; v.y += w1 * y.y; v.z += w1 * y.z; v.w += w1 * y.w;
    }
    ((float4*)out)[(size_t)t * 128 + j] = v;
}

// ---------------- launch ----------------
extern "C" void kernel_launch(void* const* d_in, const int* in_sizes, int n_in,
                              void* d_out, int out_size) {
    const float* hidden = (const float*)d_in[0];      // [4096, 512]
    const void*  idx    = d_in[1];                    // [4096, 2] int64 or int32 (auto)
    const float* wts    = (const float*)d_in[2];      // [4096, 2]
    const float* gup    = (const float*)d_in[3];      // [32, 2048, 512]
    const float* down   = (const float*)d_in[4];      // [32, 512, 1024]
    float*       out    = (float*)d_out;              // [4096, 512]

    k_detect<<<1, 256>>>((const int*)idx);
    k_dispatch<<<TK / 256, 256>>>(idx);
    k_gather<<<TK, 128>>>(hidden);

    // GEMM1 + SwiGLU fused: [EC,512] x gate/up -> g_act [EC,1024]
    k_gemm1<<<dim3(I_ / 64, CAP_ / 64, E_), 128>>>(gup);

    // GEMM2: [EC,1024] x [E,512,1024]^T -> g_y [EC,512]
    k_gemm2<<<dim3(H_ / 128, CAP_ / 64, E_), 128>>>(down);

    k_combine<<<T_, 128>>>(wts, out);
}

// round 15
// speedup vs baseline: 1.3489x; 1.0022x over previous
#include <cuda_runtime.h>
#include <cstdint>

// Problem constants
#define E_   32
#define H_   512
#define I_   1024
#define T_   4096
#define TK   8192        // T*K
#define CAP_ 512
#define EC   (E_ * CAP_) // 16384 padded rows

// ---------------- device scratch (BSS, zero-init at module load) ----------------
__device__ float g_xd[(size_t)EC * H_];          // gathered tokens   [EC, 512]   32 MB
__device__ float g_act[(size_t)EC * I_];         // swiglu result     [EC, 1024]  64 MB
__device__ float g_y[(size_t)EC * H_];           // expert output     [EC, 512]   32 MB
__device__ int   g_cnt[E_];
__device__ int   g_row[TK];                      // slot -> padded row (-1 = invalid)
__device__ int   g_mode64;                       // 1 if indices are int64, 0 if int32

__device__ __forceinline__ float2 unpack64(unsigned long long v) {
    float2 r;
    asm("mov.b64 {%0, %1}, %2;" : "=f"(r.x), "=f"(r.y) : "l"(v));
    return r;
}

// ---------------- dtype detect + zero counters ----------------
__global__ void k_detect(const int* __restrict__ idx32) {
    __shared__ int s_or;
    if (threadIdx.x == 0) s_or = 0;
    if (threadIdx.x < E_) g_cnt[threadIdx.x] = 0;
    __syncthreads();
    int acc = 0;
    for (int i = threadIdx.x; i < TK / 2; i += blockDim.x)
        acc |= idx32[2 * i + 1];
    atomicOr(&s_or, acc);
    __syncthreads();
    if (threadIdx.x == 0) g_mode64 = (s_or == 0) ? 1 : 0;
}

__global__ void k_dispatch(const void* __restrict__ idx_raw) {
    int s = blockIdx.x * blockDim.x + threadIdx.x;
    if (s >= TK) return;
    long long e;
    if (g_mode64) e = ((const long long*)idx_raw)[s];
    else          e = (long long)((const int*)idx_raw)[s];
    if (e < 0 || e >= E_) { g_row[s] = -1; return; }
    int pos = atomicAdd(&g_cnt[(int)e], 1);
    g_row[s] = (pos < CAP_) ? ((int)e * CAP_ + pos) : -1;
}

// one block per slot, 128 threads, H/4 = 128 float4 per row
__global__ void k_gather(const float* __restrict__ hidden) {
    int s = blockIdx.x;
    int r = g_row[s];
    if (r < 0) return;
    int t = s >> 1;  // K = 2
    const float4* src = (const float4*)(hidden + (size_t)t * H_);
    float4* dst = (float4*)(g_xd + (size_t)r * H_);
    dst[threadIdx.x] = src[threadIdx.x];
}

// =====================================================================
// GEMM1 fused with SwiGLU.
// Block: BM=64 rows x (64 gate + 64 up) columns, K=512, BK=16, 128 thr.
// Per thread: 8(m) x 4(gate) + 8 x 4(up) accumulators as f32x2 pairs.
// act[m][n] = silu(gate[m][n]) * up[m][n], written directly to g_act.
// =====================================================================
__global__ __launch_bounds__(128, 4) void k_gemm1(const float* __restrict__ W) {
    int e = blockIdx.z;
    int n_e = g_cnt[e]; if (n_e > CAP_) n_e = CAP_;
    int m0 = blockIdx.y * 64;
    if (m0 >= n_e) return;
    int n0 = blockIdx.x * 64;

    const float* Ae = g_xd + ((size_t)e * CAP_ + m0) * 512;
    const float* Wg = W + ((size_t)e * 2048 + n0) * 512;          // gate rows
    const float* Wu = W + ((size_t)e * 2048 + 1024 + n0) * 512;   // up rows
    float* Ce = g_act + ((size_t)e * CAP_ + m0) * 1024 + n0;

    __shared__ __align__(16) float As[2][16][64];
    __shared__ __align__(16) float Bs[2][16][128];

    int tid = threadIdx.x;
    int l = tid & 31, w = tid >> 5;      // loader: lane-row, k-chunk
    int tx = tid & 15, ty = tid >> 4;    // compute: n-group, m-group

    // loader base pointers (k-chunk = w, i.e. floats [w*4, w*4+4) of each BK tile)
    const float* ap0 = Ae + (size_t)l * 512 + w * 4;
    const float* ap1 = ap0 + (size_t)32 * 512;
    const float* bp[4];
#pragma unroll
    for (int i = 0; i < 4; i++) {
        int br = l + 32 * i;
        bp[i] = ((br < 64) ? (Wg + (size_t)br * 512)
                           : (Wu + (size_t)(br - 64) * 512)) + w * 4;
    }

    unsigned long long accg[8][2], accu[8][2];
#pragma unroll
    for (int i = 0; i < 8; i++) {
        accg[i][0] = accg[i][1] = 0ull;
        accu[i][0] = accu[i][1] = 0ull;
    }

    float4 ra0, ra1, rb[4];
    auto prefetch = [&](int kt) {
        ra0 = *(const float4*)(ap0 + kt);
        ra1 = *(const float4*)(ap1 + kt);
#pragma unroll
        for (int i = 0; i < 4; i++) rb[i] = *(const float4*)(bp[i] + kt);
    };
    auto stage = [&](int buf) {
        As[buf][w * 4 + 0][l] = ra0.x;  As[buf][w * 4 + 1][l] = ra0.y;
        As[buf][w * 4 + 2][l] = ra0.z;  As[buf][w * 4 + 3][l] = ra0.w;
        As[buf][w * 4 + 0][l + 32] = ra1.x;  As[buf][w * 4 + 1][l + 32] = ra1.y;
        As[buf][w * 4 + 2][l + 32] = ra1.z;  As[buf][w * 4 + 3][l + 32] = ra1.w;
#pragma unroll
        for (int i = 0; i < 4; i++) {
            Bs[buf][w * 4 + 0][l + 32 * i] = rb[i].x;
            Bs[buf][w * 4 + 1][l + 32 * i] = rb[i].y;
            Bs[buf][w * 4 + 2][l + 32 * i] = rb[i].z;
            Bs[buf][w * 4 + 3][l + 32 * i] = rb[i].w;
        }
    };

    prefetch(0);
    stage(0);
    __syncthreads();

    const int NK = 512 / 16;
    for (int t = 0; t < NK; t++) {
        int buf = t & 1;
        if (t + 1 < NK) prefetch((t + 1) * 16);
#pragma unroll
        for (int k = 0; k < 16; k++) {
            float4 a0 = *(const float4*)&As[buf][k][ty * 8];
            float4 a1 = *(const float4*)&As[buf][k][ty * 8 + 4];
            ulonglong2 bg = *(const ulonglong2*)&Bs[buf][k][tx * 4];
            ulonglong2 bu = *(const ulonglong2*)&Bs[buf][k][64 + tx * 4];
            float av[8] = {a0.x, a0.y, a0.z, a0.w, a1.x, a1.y, a1.z, a1.w};
#pragma unroll
            for (int i = 0; i < 8; i++) {
                unsigned long long ad;
                unsigned int au = __float_as_uint(av[i]);
                asm("mov.b64 %0, {%1, %1};" : "=l"(ad) : "r"(au));
                asm("fma.rn.f32x2 %0, %1, %2, %0;" : "+l"(accg[i][0]) : "l"(ad), "l"(bg.x));
                asm("fma.rn.f32x2 %0, %1, %2, %0;" : "+l"(accg[i][1]) : "l"(ad), "l"(bg.y));
                asm("fma.rn.f32x2 %0, %1, %2, %0;" : "+l"(accu[i][0]) : "l"(ad), "l"(bu.x));
                asm("fma.rn.f32x2 %0, %1, %2, %0;" : "+l"(accu[i][1]) : "l"(ad), "l"(bu.y));
            }
        }
        if (t + 1 < NK) stage((t + 1) & 1);
        __syncthreads();
    }

    // fused SwiGLU epilogue: act = silu(gate) * up
#pragma unroll
    for (int i = 0; i < 8; i++) {
        float2 g01 = unpack64(accg[i][0]);
        float2 g23 = unpack64(accg[i][1]);
        float2 u01 = unpack64(accu[i][0]);
        float2 u23 = unpack64(accu[i][1]);
        float4 o;
        o.x = (g01.x / (1.f + __expf(-g01.x))) * u01.x;
        o.y = (g01.y / (1.f + __expf(-g01.y))) * u01.y;
        o.z = (g23.x / (1.f + __expf(-g23.x))) * u23.x;
        o.w = (g23.y / (1.f + __expf(-g23.y))) * u23.y;
        *(float4*)(Ce + (size_t)(ty * 8 + i) * 1024 + tx * 4) = o;
    }
}

// =====================================================================
// GEMM2: y[e] = act[e] (EC x 1024) * down[e]^T (512 x 1024).
// Block: BM=64 x BN=128, K=1024, BK=16, 128 thr, 8x8 microtile.
// =====================================================================
__global__ __launch_bounds__(128, 4) void k_gemm2(const float* __restrict__ W) {
    int e = blockIdx.z;
    int n_e = g_cnt[e]; if (n_e > CAP_) n_e = CAP_;
    int m0 = blockIdx.y * 64;
    if (m0 >= n_e) return;
    int n0 = blockIdx.x * 128;

    const float* Ae = g_act + ((size_t)e * CAP_ + m0) * 1024;
    const float* We = W + ((size_t)e * 512 + n0) * 1024;
    float* Ce = g_y + ((size_t)e * CAP_ + m0) * 512 + n0;

    __shared__ __align__(16) float As[2][16][64];
    __shared__ __align__(16) float Bs[2][16][128];

    int tid = threadIdx.x;
    int l = tid & 31, w = tid >> 5;
    int tx = tid & 15, ty = tid >> 4;

    const float* ap0 = Ae + (size_t)l * 1024 + w * 4;
    const float* ap1 = ap0 + (size_t)32 * 1024;
    const float* bp[4];
#pragma unroll
    for (int i = 0; i < 4; i++)
        bp[i] = We + (size_t)(l + 32 * i) * 1024 + w * 4;

    unsigned long long acc[8][4];
#pragma unroll
    for (int i = 0; i < 8; i++)
#pragma unroll
        for (int j = 0; j < 4; j++) acc[i][j] = 0ull;

    float4 ra0, ra1, rb[4];
    auto prefetch = [&](int kt) {
        ra0 = *(const float4*)(ap0 + kt);
        ra1 = *(const float4*)(ap1 + kt);
#pragma unroll
        for (int i = 0; i < 4; i++) rb[i] = *(const float4*)(bp[i] + kt);
    };
    auto stage = [&](int buf) {
        As[buf][w * 4 + 0][l] = ra0.x;  As[buf][w * 4 + 1][l] = ra0.y;
        As[buf][w * 4 + 2][l] = ra0.z;  As[buf][w * 4 + 3][l] = ra0.w;
        As[buf][w * 4 + 0][l + 32] = ra1.x;  As[buf][w * 4 + 1][l + 32] = ra1.y;
        As[buf][w * 4 + 2][l + 32] = ra1.z;  As[buf][w * 4 + 3][l + 32] = ra1.w;
#pragma unroll
        for (int i = 0; i < 4; i++) {
            Bs[buf][w * 4 + 0][l + 32 * i] = rb[i].x;
            Bs[buf][w * 4 + 1][l + 32 * i] = rb[i].y;
            Bs[buf][w * 4 + 2][l + 32 * i] = rb[i].z;
            Bs[buf][w * 4 + 3][l + 32 * i] = rb[i].w;
        }
    };

    prefetch(0);
    stage(0);
    __syncthreads();

    const int NK = 1024 / 16;
    for (int t = 0; t < NK; t++) {
        int buf = t & 1;
        if (t + 1 < NK) prefetch((t + 1) * 16);
#pragma unroll
        for (int k = 0; k < 16; k++) {
            float4 a0 = *(const float4*)&As[buf][k][ty * 8];
            float4 a1 = *(const float4*)&As[buf][k][ty * 8 + 4];
            ulonglong2 b0 = *(const ulonglong2*)&Bs[buf][k][tx * 8];
            ulonglong2 b1 = *(const ulonglong2*)&Bs[buf][k][tx * 8 + 4];
            unsigned long long bpk[4] = {b0.x, b0.y, b1.x, b1.y};
            float av[8] = {a0.x, a0.y, a0.z, a0.w, a1.x, a1.y, a1.z, a1.w};
#pragma unroll
            for (int i = 0; i < 8; i++) {
                unsigned long long ad;
                unsigned int au = __float_as_uint(av[i]);
                asm("mov.b64 %0, {%1, %1};" : "=l"(ad) : "r"(au));
#pragma unroll
                for (int j = 0; j < 4; j++)
                    asm("fma.rn.f32x2 %0, %1, %2, %0;"
                        : "+l"(acc[i][j]) : "l"(ad), "l"(bpk[j]));
            }
        }
        if (t + 1 < NK) stage((t + 1) & 1);
        __syncthreads();
    }

#pragma unroll
    for (int i = 0; i < 8; i++) {
        float* cr = Ce + (size_t)(ty * 8 + i) * 512 + tx * 8;
        ulonglong2 v0; v0.x = acc[i][0]; v0.y = acc[i][1];
        ulonglong2 v1; v1.x = acc[i][2]; v1.y = acc[i][3];
        *(ulonglong2*)cr = v0;
        *(ulonglong2*)(cr + 4) = v1;
    }
}

// ---------------- combine: out[t] = sum_k w[t,k] * y[row(t,k)] ----------------
__global__ void k_combine(const float* __restrict__ wts, float* __restrict__ out) {
    int t = blockIdx.x;
    int r0 = g_row[2 * t];
    int r1 = g_row[2 * t + 1];
    float w0 = wts[2 * t];
    float w1 = wts[2 * t + 1];
    int j = threadIdx.x;  // 0..127 (H/4)
    float4 v = {0.f, 0.f, 0.f, 0.f};
    if (r0 >= 0) {
        float4 y = ((const float4*)g_y)[(size_t)r0 * 128 + j];
        v.x += w0 * y.x; v.y += w0 * y.y; v.z += w0 * y.z; v.w += w0 * y.w;
    }
    if (r1 >= 0) {
        float4 y = ((const float4*)g_y)[(size_t)r1 * 128 + j];
        v.x += w1 * y.x; v.y += w1 * y.y; v.z += w1 * y.z; v.w += w1 * y.w;
    }
    ((float4*)out)[(size_t)t * 128 + j] = v;
}

// ---------------- launch ----------------
extern "C" void kernel_launch(void* const* d_in, const int* in_sizes, int n_in,
                              void* d_out, int out_size) {
    const float* hidden = (const float*)d_in[0];      // [4096, 512]
    const void*  idx    = d_in[1];                    // [4096, 2] int64 or int32 (auto)
    const float* wts    = (const float*)d_in[2];      // [4096, 2]
    const float* gup    = (const float*)d_in[3];      // [32, 2048, 512]
    const float* down   = (const float*)d_in[4];      // [32, 512, 1024]
    float*       out    = (float*)d_out;              // [4096, 512]

    k_detect<<<1, 256>>>((const int*)idx);
    k_dispatch<<<TK / 256, 256>>>(idx);
    k_gather<<<TK, 128>>>(hidden);

    // GEMM1 + SwiGLU fused: [EC,512] x gate/up -> g_act [EC,1024]
    k_gemm1<<<dim3(I_ / 64, CAP_ / 64, E_), 128>>>(gup);

    // GEMM2: [EC,1024] x [E,512,1024]^T -> g_y [EC,512]
    k_gemm2<<<dim3(H_ / 128, CAP_ / 64, E_), 128>>>(down);

    k_combine<<<T_, 128>>>(wts, out);
}